// round 16
// baseline (speedup 1.0000x reference)
#include <cuda_runtime.h>

// RSA_layer: output = c[-1] only  =>  softmax needed only for row i=1023.
//   s[j,u] = (fs @ w_hi)[j,u] + q[j]*w_dot[u],   q[j] = x . fs[j]
//   out[u] = sum_j fs[j,u]*exp(s[j,u]) / sum_j exp(s[j,u])
// Logits O(1) => exp without max-subtraction (validated rel_err ~3e-7).
// fs[j,v] = state[v*1024 + j + 1] for j < 1023;  fs[1023,v] = x[v]
//
// R16 = R15 + symmetric epilogue ISOLATED (R12 bundled it with the polling
// regression; never tested alone):
//  - both halves publish partials, both compute exp
//  - half-0 REDGs z, half-1 REDGs c  (1 REDG/thread instead of 2, halves
//    balanced, bar's last arrival moves earlier)
//  - epilogue row reads via LDS.128 (scalar reads were 8-way bank-conflicted)

#define UNITS 128
#define WIN   1024
#define NBLK  128         // worker blocks; block NBLK is the poller
#define TPB   256
#define JB    8           // j-rows per worker block
#define VH    64          // v-range per half
#define NBANK 4

typedef unsigned long long u64;

__device__ float2 g_acc[NBANK][UNITS];   // zeroed at load; reset each replay
__device__ unsigned int g_cnt = 0;

__device__ __forceinline__ u64 pack2(float lo, float hi) {
    u64 r;
    asm("mov.b64 %0, {%1, %2};" : "=l"(r) : "f"(lo), "f"(hi));
    return r;
}
__device__ __forceinline__ void unpack2(u64 p, float& lo, float& hi) {
    asm("mov.b64 {%0, %1}, %2;" : "=f"(lo), "=f"(hi) : "l"(p));
}
__device__ __forceinline__ u64 ffma2(u64 a, u64 b, u64 c) {
    u64 d;
    asm("fma.rn.f32x2 %0, %1, %2, %3;" : "=l"(d) : "l"(a), "l"(b), "l"(c));
    return d;
}

__global__ void __launch_bounds__(TPB)
rsa_fused(const float* __restrict__ x,
          const float* __restrict__ state,
          const float* __restrict__ w,
          float* __restrict__ out)
{
    __shared__ __align__(16) float fs_sh[UNITS][JB];   // [v][j], j contiguous (4KB)
    __shared__ float x_sh[UNITS];
    __shared__ float q_sh[JB];
    __shared__ __align__(16) float comb0[UNITS][JB];   // half-0 partials (4KB)
    __shared__ __align__(16) float comb1[UNITS][JB];   // half-1 partials (4KB)

    const int t = threadIdx.x;

    // ---------------- Poller block: warp 0 only ------------------------------
    if (blockIdx.x == NBLK) {
        if (t < 32) {
            unsigned int v;
            do {   // 32 lanes, one line -> one wavefront per poll iteration
                asm volatile("ld.acquire.gpu.global.u32 %0, [%1];"
                             : "=r"(v) : "l"(&g_cnt) : "memory");
            } while (v != NBLK);
            // Lane finalizes u = 4t..4t+3: 8 independent LDG.128, one round.
            float4 a0 = *(const float4*)&g_acc[0][4 * t];
            float4 a1 = *(const float4*)&g_acc[0][4 * t + 2];
            float4 b0 = *(const float4*)&g_acc[1][4 * t];
            float4 b1 = *(const float4*)&g_acc[1][4 * t + 2];
            float4 c0 = *(const float4*)&g_acc[2][4 * t];
            float4 c1 = *(const float4*)&g_acc[2][4 * t + 2];
            float4 d0 = *(const float4*)&g_acc[3][4 * t];
            float4 d1 = *(const float4*)&g_acc[3][4 * t + 2];
            float4 s0 = make_float4(a0.x + b0.x + c0.x + d0.x,
                                    a0.y + b0.y + c0.y + d0.y,
                                    a0.z + b0.z + c0.z + d0.z,
                                    a0.w + b0.w + c0.w + d0.w);
            float4 s1 = make_float4(a1.x + b1.x + c1.x + d1.x,
                                    a1.y + b1.y + c1.y + d1.y,
                                    a1.z + b1.z + c1.z + d1.z,
                                    a1.w + b1.w + c1.w + d1.w);
            *(float4*)&out[4 * t] =
                make_float4(s0.y / s0.x, s0.w / s0.z, s1.y / s1.x, s1.w / s1.z);
            float4 zz = make_float4(0.f, 0.f, 0.f, 0.f);
            #pragma unroll
            for (int bk = 0; bk < NBANK; bk++) {       // reset for next replay
                *(float4*)&g_acc[bk][4 * t]     = zz;
                *(float4*)&g_acc[bk][4 * t + 2] = zz;
            }
            if (t == 0) g_cnt = 0;
        }
        return;
    }

    // ---------------- Worker blocks -----------------------------------------
    const int u  = t & (UNITS - 1);       // output column
    const int h  = t >> 7;                // v-half: 0 -> v[0,64), 1 -> v[64,128)
    const int j0 = blockIdx.x * JB;

    if (t < UNITS) x_sh[t] = x[t];

    // fs tile: 128v x 8j = 1024 floats, 4 per thread.
    #pragma unroll
    for (int k = 0; k < 4; k++) {
        int i = t + k * TPB;
        int v = i >> 3, j = i & (JB - 1);
        int jj = j0 + j;
        fs_sh[v][j] = (jj < WIN - 1) ? state[v * WIN + jj + 1] : x[v];
    }

    // This thread's 64-v slice of w_hi column u: 64 independent LDGs.
    const float* __restrict__ wu = w + h * VH * UNITS + u;  // w_hi[h*64+i][u]
    const float wd = w[2 * UNITS * UNITS + u];              // w_dot[u]
    float wr[VH];
    #pragma unroll
    for (int i = 0; i < VH; i++) wr[i] = wu[i * UNITS];

    __syncthreads();   // fs_sh / x_sh ready

    // q[j] = fs[j].x : 8 warps, warp jw owns one j (BEFORE the GEMM: shuffle
    // latency hides under other warps' GEMM issue — R14 proved the converse).
    {
        const int warp = t >> 5, lane = t & 31;
        float p = fs_sh[lane][warp]      * x_sh[lane]
                + fs_sh[lane + 32][warp] * x_sh[lane + 32]
                + fs_sh[lane + 64][warp] * x_sh[lane + 64]
                + fs_sh[lane + 96][warp] * x_sh[lane + 96];
        #pragma unroll
        for (int o = 16; o; o >>= 1) p += __shfl_xor_sync(0xffffffffu, p, o);
        if (lane == 0) q_sh[warp] = p;
    }

    // Partial GEMM over this half's v: {2x LDS.128 + 4x FFMA2} per v.
    u64 s01 = 0, s23 = 0, s45 = 0, s67 = 0;
    #pragma unroll
    for (int i = 0; i < VH; i++) {
        u64 w2 = pack2(wr[i], wr[i]);                 // alu-pipe
        const ulonglong2* fp = (const ulonglong2*)fs_sh[h * VH + i];
        ulonglong2 f = fp[0];                         // j0..3 broadcast
        s01 = ffma2(f.x, w2, s01);
        s23 = ffma2(f.y, w2, s23);
        ulonglong2 g = fp[1];                         // j4..7 broadcast
        s45 = ffma2(g.x, w2, s45);
        s67 = ffma2(g.y, w2, s67);
    }

    float sp[JB];
    unpack2(s01, sp[0], sp[1]);
    unpack2(s23, sp[2], sp[3]);
    unpack2(s45, sp[4], sp[5]);
    unpack2(s67, sp[6], sp[7]);

    // Symmetric exchange: BOTH halves publish (2x STS.128 each).
    {
        float (*mine)[JB] = (h == 0) ? comb0 : comb1;
        *(float4*)&mine[u][0] = make_float4(sp[0], sp[1], sp[2], sp[3]);
        *(float4*)&mine[u][4] = make_float4(sp[4], sp[5], sp[6], sp[7]);
    }
    __syncthreads();   // publishes comb + q_sh

    // Both halves compute s/exp; half-0 reduces z, half-1 reduces c.
    // Row fetches as LDS.128 (scalar was 8-way bank-conflicted).
    {
        const float (*oth)[JB] = (h == 0) ? comb1 : comb0;
        float4 o0 = *(const float4*)&oth[u][0];
        float4 o1 = *(const float4*)&oth[u][4];
        float4 r0 = *(const float4*)&fs_sh[u][0];
        float4 r1 = *(const float4*)&fs_sh[u][4];
        float os[JB] = {o0.x, o0.y, o0.z, o0.w, o1.x, o1.y, o1.z, o1.w};
        float fr[JB] = {r0.x, r0.y, r0.z, r0.w, r1.x, r1.y, r1.z, r1.w};
        float acc = 0.0f;
        #pragma unroll
        for (int j = 0; j < JB; j++) {
            float e = __expf(fmaf(q_sh[j], wd, sp[j] + os[j]));
            acc += (h == 0) ? e : e * fr[j];          // z : c (h warp-uniform)
        }
        float2* bank = g_acc[blockIdx.x & (NBANK - 1)];
        float* dst = (h == 0) ? &bank[u].x : &bank[u].y;
        atomicAdd(dst, acc);                          // relaxed RED.ADD
    }

    // bar.sync + t0 release covers the block's REDGs (PTX model: release
    // composes through bar). No MEMBAR.
    __syncthreads();
    if (t == 0)
        asm volatile("red.add.release.gpu.global.u32 [%0], %1;"
                     :: "l"(&g_cnt), "r"(1u) : "memory");
}

extern "C" void kernel_launch(void* const* d_in, const int* in_sizes, int n_in,
                              void* d_out, int out_size)
{
    const float* x     = (const float*)d_in[0];   // input_tensor (1,128)
    const float* state = (const float*)d_in[1];   // state (128,1024)
    const float* w     = (const float*)d_in[2];   // w (257,128)
    // d_in[3] = b — cancels inside the softmax, unused.

    rsa_fused<<<NBLK + 1, TPB>>>(x, state, w, (float*)d_out);
}

// round 17
// speedup vs baseline: 1.2518x; 1.2518x over previous
#include <cuda_runtime.h>

// RSA_layer: output = c[-1] only  =>  softmax needed only for row i=1023.
//   s[j,u] = (fs @ w_hi)[j,u] + q[j]*w_dot[u],   q[j] = x . fs[j]
//   out[u] = sum_j fs[j,u]*exp(s[j,u]) / sum_j exp(s[j,u])
// Logits O(1) => exp without max-subtraction (validated rel_err ~3e-7).
// fs[j,v] = state[v*1024 + j + 1] for j < 1023;  fs[1023,v] = x[v]
//
// R17 = R15 (best, 10.752) + transposed shadow tile fs_t[j][v]:
//  - written during the load phase (8-way-conflicted STS, but fire-and-forget
//    and hidden under the DRAM wait)
//  - q-phase and epilogue-c reads become conflict-free (were 8-way conflicted
//    column/row reads of fs_sh) -> ~150-300 cycles off the critical path.
// (R16 showed symmetric epilogue regresses; q stays BEFORE the GEMM per R14.)

#define UNITS 128
#define WIN   1024
#define NBLK  128         // worker blocks; block NBLK is the poller
#define TPB   256
#define JB    8           // j-rows per worker block
#define VH    64          // v-range per half
#define NBANK 4

typedef unsigned long long u64;

__device__ float2 g_acc[NBANK][UNITS];   // zeroed at load; reset each replay
__device__ unsigned int g_cnt = 0;

__device__ __forceinline__ u64 pack2(float lo, float hi) {
    u64 r;
    asm("mov.b64 %0, {%1, %2};" : "=l"(r) : "f"(lo), "f"(hi));
    return r;
}
__device__ __forceinline__ void unpack2(u64 p, float& lo, float& hi) {
    asm("mov.b64 {%0, %1}, %2;" : "=f"(lo), "=f"(hi) : "l"(p));
}
__device__ __forceinline__ u64 ffma2(u64 a, u64 b, u64 c) {
    u64 d;
    asm("fma.rn.f32x2 %0, %1, %2, %3;" : "=l"(d) : "l"(a), "l"(b), "l"(c));
    return d;
}

__global__ void __launch_bounds__(TPB)
rsa_fused(const float* __restrict__ x,
          const float* __restrict__ state,
          const float* __restrict__ w,
          float* __restrict__ out)
{
    __shared__ __align__(16) float fs_sh[UNITS][JB];   // [v][j] for GEMM (4KB)
    __shared__ __align__(16) float fs_t[JB][UNITS];    // [j][v] shadow (4KB)
    __shared__ float x_sh[UNITS];
    __shared__ float q_sh[JB];
    __shared__ __align__(16) float comb[UNITS][JB];    // half-1 partials (4KB)

    const int t = threadIdx.x;

    // ---------------- Poller block: warp 0 only ------------------------------
    if (blockIdx.x == NBLK) {
        if (t < 32) {
            unsigned int v;
            do {   // 32 lanes, one line -> one wavefront per poll iteration
                asm volatile("ld.acquire.gpu.global.u32 %0, [%1];"
                             : "=r"(v) : "l"(&g_cnt) : "memory");
            } while (v != NBLK);
            // Lane finalizes u = 4t..4t+3: 8 independent LDG.128, one round.
            float4 a0 = *(const float4*)&g_acc[0][4 * t];
            float4 a1 = *(const float4*)&g_acc[0][4 * t + 2];
            float4 b0 = *(const float4*)&g_acc[1][4 * t];
            float4 b1 = *(const float4*)&g_acc[1][4 * t + 2];
            float4 c0 = *(const float4*)&g_acc[2][4 * t];
            float4 c1 = *(const float4*)&g_acc[2][4 * t + 2];
            float4 d0 = *(const float4*)&g_acc[3][4 * t];
            float4 d1 = *(const float4*)&g_acc[3][4 * t + 2];
            float4 s0 = make_float4(a0.x + b0.x + c0.x + d0.x,
                                    a0.y + b0.y + c0.y + d0.y,
                                    a0.z + b0.z + c0.z + d0.z,
                                    a0.w + b0.w + c0.w + d0.w);
            float4 s1 = make_float4(a1.x + b1.x + c1.x + d1.x,
                                    a1.y + b1.y + c1.y + d1.y,
                                    a1.z + b1.z + c1.z + d1.z,
                                    a1.w + b1.w + c1.w + d1.w);
            *(float4*)&out[4 * t] =
                make_float4(s0.y / s0.x, s0.w / s0.z, s1.y / s1.x, s1.w / s1.z);
            float4 zz = make_float4(0.f, 0.f, 0.f, 0.f);
            #pragma unroll
            for (int bk = 0; bk < NBANK; bk++) {       // reset for next replay
                *(float4*)&g_acc[bk][4 * t]     = zz;
                *(float4*)&g_acc[bk][4 * t + 2] = zz;
            }
            if (t == 0) g_cnt = 0;
        }
        return;
    }

    // ---------------- Worker blocks -----------------------------------------
    const int u  = t & (UNITS - 1);       // output column
    const int h  = t >> 7;                // v-half: 0 -> v[0,64), 1 -> v[64,128)
    const int j0 = blockIdx.x * JB;

    if (t < UNITS) x_sh[t] = x[t];

    // fs tile: 128v x 8j, 4 per thread; dual store (fs_sh + transposed fs_t).
    // fs_t STS is 8-way conflicted but fire-and-forget under the DRAM wait.
    #pragma unroll
    for (int k = 0; k < 4; k++) {
        int i = t + k * TPB;
        int v = i >> 3, j = i & (JB - 1);
        int jj = j0 + j;
        float val = (jj < WIN - 1) ? state[v * WIN + jj + 1] : x[v];
        fs_sh[v][j] = val;
        fs_t[j][v]  = val;
    }

    // This thread's 64-v slice of w_hi column u: 64 independent LDGs.
    const float* __restrict__ wu = w + h * VH * UNITS + u;  // w_hi[h*64+i][u]
    const float wd = w[2 * UNITS * UNITS + u];              // w_dot[u]
    float wr[VH];
    #pragma unroll
    for (int i = 0; i < VH; i++) wr[i] = wu[i * UNITS];

    __syncthreads();   // fs_sh / fs_t / x_sh ready

    // q[j] = fs[j].x : warp jw owns j=jw; conflict-free row reads of fs_t.
    {
        const int warp = t >> 5, lane = t & 31;
        float p = fs_t[warp][lane]      * x_sh[lane]
                + fs_t[warp][lane + 32] * x_sh[lane + 32]
                + fs_t[warp][lane + 64] * x_sh[lane + 64]
                + fs_t[warp][lane + 96] * x_sh[lane + 96];
        #pragma unroll
        for (int o = 16; o; o >>= 1) p += __shfl_xor_sync(0xffffffffu, p, o);
        if (lane == 0) q_sh[warp] = p;
    }

    // Partial GEMM over this half's v: {2x LDS.128 + 4x FFMA2} per v.
    u64 s01 = 0, s23 = 0, s45 = 0, s67 = 0;
    #pragma unroll
    for (int i = 0; i < VH; i++) {
        u64 w2 = pack2(wr[i], wr[i]);                 // alu-pipe
        const ulonglong2* fp = (const ulonglong2*)fs_sh[h * VH + i];
        ulonglong2 f = fp[0];                         // j0..3 broadcast
        s01 = ffma2(f.x, w2, s01);
        s23 = ffma2(f.y, w2, s23);
        ulonglong2 g = fp[1];                         // j4..7 broadcast
        s45 = ffma2(g.x, w2, s45);
        s67 = ffma2(g.y, w2, s67);
    }

    float sp[JB];
    unpack2(s01, sp[0], sp[1]);
    unpack2(s23, sp[2], sp[3]);
    unpack2(s45, sp[4], sp[5]);
    unpack2(s67, sp[6], sp[7]);

    // Half-1 publishes its partials (2x STS.128).
    if (h == 1) {
        *(float4*)&comb[u][0] = make_float4(sp[0], sp[1], sp[2], sp[3]);
        *(float4*)&comb[u][4] = make_float4(sp[4], sp[5], sp[6], sp[7]);
    }
    __syncthreads();   // also publishes q_sh

    // Half-0 combines, applies q*wd, REDG-accumulates into this block's bank.
    // fs weights read from fs_t[j][u]: consecutive lanes -> conflict-free.
    if (h == 0) {
        float z = 0.0f, c = 0.0f;
        #pragma unroll
        for (int j = 0; j < JB; j++) {
            float sj = sp[j] + comb[u][j];
            float e  = __expf(fmaf(q_sh[j], wd, sj));
            z += e;
            c = fmaf(e, fs_t[j][u], c);               // conflict-free
        }
        float2* bank = g_acc[blockIdx.x & (NBANK - 1)];
        atomicAdd(&bank[u].x, z);                     // relaxed RED.ADD
        atomicAdd(&bank[u].y, c);
    }

    // bar.sync + t0 release covers the block's REDGs (PTX model: release
    // composes through bar). No MEMBAR.
    __syncthreads();
    if (t == 0)
        asm volatile("red.add.release.gpu.global.u32 [%0], %1;"
                     :: "l"(&g_cnt), "r"(1u) : "memory");
}

extern "C" void kernel_launch(void* const* d_in, const int* in_sizes, int n_in,
                              void* d_out, int out_size)
{
    const float* x     = (const float*)d_in[0];   // input_tensor (1,128)
    const float* state = (const float*)d_in[1];   // state (128,1024)
    const float* w     = (const float*)d_in[2];   // w (257,128)
    // d_in[3] = b — cancels inside the softmax, unused.

    rsa_fused<<<NBLK + 1, TPB>>>(x, state, w, (float*)d_out);
}